// round 1
// baseline (speedup 1.0000x reference)
#include <cuda_runtime.h>
#include <cstdint>
#include <cstddef>

// ---------------- problem constants ----------------
#define RB 8192
#define RE 256
#define RNE 4096
#define RNL 3

// output layout (float32 elements), tuple order:
// x_q [B,E], mean_loss [1], all_idx [B,L], all_oh [B,L,NE], all_logits [B,L,NE]
static constexpr size_t LEN_XQ  = (size_t)RB * RE;                 // 2097152
static constexpr size_t OFF_LOSS = LEN_XQ;                         // 2097152
static constexpr size_t OFF_IDX  = OFF_LOSS + 1;                   // 2097153
static constexpr size_t LEN_IDX  = (size_t)RB * RNL;               // 24576
static constexpr size_t OFF_OH   = OFF_IDX + LEN_IDX;              // 2121729
static constexpr size_t LEN_OH   = (size_t)RB * RNL * RNE;         // 100663296
static constexpr size_t OFF_LG   = OFF_OH + LEN_OH;                // 102785025

// ---------------- device scratch (no allocations allowed) ----------------
__device__ float g_res[RB * RE];                 // residual [B,E]
__device__ float g_rr[RB];                       // ||residual_b||^2 per row
__device__ float g_cc[RNL * RNE];                // ||codebook row||^2
__device__ unsigned long long g_keys[RB];        // packed (dist_bits<<32 | idx)
__device__ float g_lossrow[RB];                  // per-row accumulated sq error

// ---------------- init: residual = x, rr, zero x_q, reset keys/loss ----------------
__global__ void k_init_rows(const float* __restrict__ x, float* __restrict__ out) {
    int b = blockIdx.x, t = threadIdx.x;  // 64 threads, one row per block
    float4 v = *(const float4*)(x + (size_t)b * RE + t * 4);
    *(float4*)(g_res + (size_t)b * RE + t * 4) = v;
    *(float4*)(out + (size_t)b * RE + t * 4) = make_float4(0.f, 0.f, 0.f, 0.f);
    float s = v.x * v.x + v.y * v.y + v.z * v.z + v.w * v.w;
    for (int o = 16; o > 0; o >>= 1) s += __shfl_down_sync(0xffffffffu, s, o);
    __shared__ float sm[2];
    if ((t & 31) == 0) sm[t >> 5] = s;
    __syncthreads();
    if (t == 0) {
        g_rr[b] = sm[0] + sm[1];
        g_keys[b] = 0xFFFFFFFFFFFFFFFFULL;
        g_lossrow[b] = 0.f;
    }
}

// codebook row norms: one block per (layer*NE + j)
__global__ void k_init_cc(const float* __restrict__ cbs) {
    int i = blockIdx.x, t = threadIdx.x;  // 64 threads
    float4 v = *(const float4*)(cbs + (size_t)i * RE + t * 4);
    float s = v.x * v.x + v.y * v.y + v.z * v.z + v.w * v.w;
    for (int o = 16; o > 0; o >>= 1) s += __shfl_down_sync(0xffffffffu, s, o);
    __shared__ float sm[2];
    if ((t & 31) == 0) sm[t >> 5] = s;
    __syncthreads();
    if (t == 0) g_cc[i] = sm[0] + sm[1];
}

// zero the one-hot region (base offset is odd -> fix alignment, then float4)
__global__ void k_zero_oh(float* __restrict__ out) {
    const size_t n4 = (LEN_OH - 3) / 4;  // 25165823, remainder 1
    float4* p = (float4*)(out + OFF_OH + 3);
    size_t i = (size_t)blockIdx.x * blockDim.x + threadIdx.x;
    size_t stride = (size_t)gridDim.x * blockDim.x;
    for (size_t j = i; j < n4; j += stride) p[j] = make_float4(0.f, 0.f, 0.f, 0.f);
    if (i == 0) {
        out[OFF_OH + 0] = 0.f;
        out[OFF_OH + 1] = 0.f;
        out[OFF_OH + 2] = 0.f;
        out[OFF_OH + 3 + n4 * 4] = 0.f;
    }
}

// ---------------- distance GEMM + logits + argmin ----------------
// tile: BM=64 rows x BN=128 cols, BK=32, 256 threads, 8x4 microtile per thread
__global__ void __launch_bounds__(256) k_dist(const float* __restrict__ cbs, int l,
                                              float* __restrict__ out) {
    __shared__ __align__(16) char smraw[32 * 68 * 4 + 32 * 132 * 4];  // 25600 B
    float* As = (float*)smraw;                   // [32][68]  (k-major, padded)
    float* Bs = (float*)(smraw + 32 * 68 * 4);   // [32][132]
    const float* cbL = cbs + (size_t)l * RNE * RE;
    const float* ccn = g_cc + l * RNE;

    int tid = threadIdx.x;
    int tx = tid & 31, ty = tid >> 5;
    int m0 = blockIdx.y * 64, n0 = blockIdx.x * 128;

    float acc[8][4];
#pragma unroll
    for (int i = 0; i < 8; i++)
#pragma unroll
        for (int j = 0; j < 4; j++) acc[i][j] = 0.f;

    for (int kt = 0; kt < RE; kt += 32) {
        // load residual tile (64 rows x 32 k), store transposed
#pragma unroll
        for (int i = 0; i < 2; i++) {
            int idx = tid + i * 256;
            int row = idx >> 3, kq = (idx & 7) * 4;
            float4 v = *(const float4*)(g_res + (size_t)(m0 + row) * RE + kt + kq);
            As[(kq + 0) * 68 + row] = v.x;
            As[(kq + 1) * 68 + row] = v.y;
            As[(kq + 2) * 68 + row] = v.z;
            As[(kq + 3) * 68 + row] = v.w;
        }
        // load codebook tile (128 cols x 32 k), store transposed
#pragma unroll
        for (int i = 0; i < 4; i++) {
            int idx = tid + i * 256;
            int col = idx >> 3, kq = (idx & 7) * 4;
            float4 v = *(const float4*)(cbL + (size_t)(n0 + col) * RE + kt + kq);
            Bs[(kq + 0) * 132 + col] = v.x;
            Bs[(kq + 1) * 132 + col] = v.y;
            Bs[(kq + 2) * 132 + col] = v.z;
            Bs[(kq + 3) * 132 + col] = v.w;
        }
        __syncthreads();
#pragma unroll 8
        for (int k = 0; k < 32; k++) {
            float4 b4 = *(const float4*)(Bs + k * 132 + tx * 4);
            float4 a0 = *(const float4*)(As + k * 68 + ty * 8);
            float4 a1 = *(const float4*)(As + k * 68 + ty * 8 + 4);
            float a[8] = {a0.x, a0.y, a0.z, a0.w, a1.x, a1.y, a1.z, a1.w};
            float bb[4] = {b4.x, b4.y, b4.z, b4.w};
#pragma unroll
            for (int i = 0; i < 8; i++)
#pragma unroll
                for (int j = 0; j < 4; j++) acc[i][j] = fmaf(a[i], bb[j], acc[i][j]);
        }
        __syncthreads();
    }

    // epilogue: d = (rr + cc) - 2*dot (mirrors reference op order), write logits,
    // per-thread row mins with lowest-index tiebreak via packed key
    unsigned long long rowkey[8];
#pragma unroll
    for (int i = 0; i < 8; i++) {
        int b = m0 + ty * 8 + i;
        float rr = g_rr[b];
        size_t lbase = OFF_LG + ((size_t)b * RNL + l) * RNE + n0 + tx * 4;
        unsigned long long best = 0xFFFFFFFFFFFFFFFFULL;
#pragma unroll
        for (int j = 0; j < 4; j++) {
            int n = n0 + tx * 4 + j;
            float d = __fadd_rn(__fadd_rn(rr, ccn[n]), -2.0f * acc[i][j]);
            out[lbase + j] = d;  // scalar store (region offset is odd, no v4)
            unsigned long long key =
                ((unsigned long long)__float_as_uint(d) << 32) | (unsigned)n;
            if (key < best) best = key;
        }
        rowkey[i] = best;
    }

    __syncthreads();  // done with As/Bs, reuse smem for reduction
    unsigned long long* Red = (unsigned long long*)smraw;  // [64][33] = 16896 B
#pragma unroll
    for (int i = 0; i < 8; i++) Red[(ty * 8 + i) * 33 + tx] = rowkey[i];
    __syncthreads();
    if (tid < 64) {
        unsigned long long mk = Red[tid * 33];
        for (int t = 1; t < 32; t++) {
            unsigned long long v = Red[tid * 33 + t];
            if (v < mk) mk = v;
        }
        atomicMin(&g_keys[m0 + tid], mk);
    }
}

// ---------------- per-row gather/update ----------------
__global__ void k_update(const float* __restrict__ cbs, int l, float* __restrict__ out) {
    int b = blockIdx.x, t = threadIdx.x;  // 64 threads
    unsigned long long key = g_keys[b];
    unsigned idx = (unsigned)(key & 0xFFFFFFFFULL);
    const float* cbL = cbs + (size_t)l * RNE * RE;
    float4 c4 = *(const float4*)(cbL + (size_t)idx * RE + t * 4);
    float4 r4 = *(float4*)(g_res + (size_t)b * RE + t * 4);

    float sq = 0.f, rrn = 0.f;
    float4 xres, nr;
    {
        float df = __fsub_rn(c4.x, r4.x);
        float xr = __fadd_rn(r4.x, df);   // straight-through: r + (c - r)
        float nv = __fsub_rn(r4.x, xr);   // residual update
        sq = fmaf(df, df, sq); rrn = fmaf(nv, nv, rrn);
        xres.x = xr; nr.x = nv;
    }
    {
        float df = __fsub_rn(c4.y, r4.y);
        float xr = __fadd_rn(r4.y, df);
        float nv = __fsub_rn(r4.y, xr);
        sq = fmaf(df, df, sq); rrn = fmaf(nv, nv, rrn);
        xres.y = xr; nr.y = nv;
    }
    {
        float df = __fsub_rn(c4.z, r4.z);
        float xr = __fadd_rn(r4.z, df);
        float nv = __fsub_rn(r4.z, xr);
        sq = fmaf(df, df, sq); rrn = fmaf(nv, nv, rrn);
        xres.z = xr; nr.z = nv;
    }
    {
        float df = __fsub_rn(c4.w, r4.w);
        float xr = __fadd_rn(r4.w, df);
        float nv = __fsub_rn(r4.w, xr);
        sq = fmaf(df, df, sq); rrn = fmaf(nv, nv, rrn);
        xres.w = xr; nr.w = nv;
    }

    *(float4*)(g_res + (size_t)b * RE + t * 4) = nr;

    float4* xq = (float4*)(out + (size_t)b * RE) + t;  // x_q accumulate
    float4 q = *xq;
    q.x += xres.x; q.y += xres.y; q.z += xres.z; q.w += xres.w;
    *xq = q;

    for (int o = 16; o > 0; o >>= 1) {
        sq += __shfl_down_sync(0xffffffffu, sq, o);
        rrn += __shfl_down_sync(0xffffffffu, rrn, o);
    }
    __shared__ float smq[2], smr[2];
    if ((t & 31) == 0) { smq[t >> 5] = sq; smr[t >> 5] = rrn; }
    __syncthreads();
    if (t == 0) {
        g_lossrow[b] += smq[0] + smq[1];
        g_rr[b] = smr[0] + smr[1];
        out[OFF_IDX + (size_t)b * RNL + l] = (float)idx;
        out[OFF_OH + ((size_t)b * RNL + l) * RNE + idx] = 1.0f;
        g_keys[b] = 0xFFFFFFFFFFFFFFFFULL;  // reset for next layer
    }
}

// ---------------- deterministic final loss reduction ----------------
__global__ void k_loss(float* __restrict__ out) {
    __shared__ float sm[256];
    int t = threadIdx.x;
    float s = 0.f;
    for (int i = t; i < RB; i += 256) s += g_lossrow[i];
    sm[t] = s;
    __syncthreads();
    for (int o = 128; o > 0; o >>= 1) {
        if (t < o) sm[t] += sm[t + o];
        __syncthreads();
    }
    // loss_l = (1 + 0.25) * mean((c - r)^2); mean over 3 layers
    if (t == 0) out[OFF_LOSS] = sm[0] * (1.25f / (3.0f * RB * RE));
}

// ---------------- launch ----------------
extern "C" void kernel_launch(void* const* d_in, const int* in_sizes, int n_in,
                              void* d_out, int out_size) {
    const float* x = (const float*)d_in[0];
    const float* cbs = (const float*)d_in[1];
    float* out = (float*)d_out;

    k_init_rows<<<RB, 64>>>(x, out);
    k_init_cc<<<RNL * RNE, 64>>>(cbs);
    k_zero_oh<<<12288, 256>>>(out);

    for (int l = 0; l < RNL; l++) {
        k_dist<<<dim3(32, 128), 256>>>(cbs, l, out);
        k_update<<<RB, 64>>>(cbs, l, out);
    }
    k_loss<<<1, 256>>>(out);
}

// round 3
// speedup vs baseline: 2.2961x; 2.2961x over previous
#include <cuda_runtime.h>
#include <cuda_bf16.h>
#include <cstdint>
#include <cstddef>

// ---------------- problem constants ----------------
#define RB 8192
#define RE 256
#define RNE 4096
#define RNL 3
#define K3 768           // split-bf16 K: [hi | lo | hi] x [hi | hi | lo]

// output layout (float32 elements), tuple order:
// x_q [B,E], mean_loss [1], all_idx [B,L], all_oh [B,L,NE], all_logits [B,L,NE]
static constexpr size_t LEN_XQ  = (size_t)RB * RE;                 // 2097152
static constexpr size_t OFF_LOSS = LEN_XQ;                         // 2097152
static constexpr size_t OFF_IDX  = OFF_LOSS + 1;                   // 2097153
static constexpr size_t LEN_IDX  = (size_t)RB * RNL;               // 24576
static constexpr size_t OFF_OH   = OFF_IDX + LEN_IDX;              // 2121729
static constexpr size_t LEN_OH   = (size_t)RB * RNL * RNE;         // 100663296
static constexpr size_t OFF_LG   = OFF_OH + LEN_OH;                // 102785025

// ---------------- device scratch ----------------
__device__ float g_res[RB * RE];                  // residual [B,E] fp32
__device__ float g_rr[RB];                        // ||residual_b||^2
__device__ float g_cc[RNL * RNE];                 // ||codebook row||^2 (fp32 exact)
__device__ unsigned long long g_keys[RB];         // packed (dist_bits<<32 | idx)
__device__ float g_lossrow[RB];                   // per-row accumulated sq error
__device__ __nv_bfloat16 g_Ap[(size_t)RB * K3];   // residual split  [hi|lo|hi]
__device__ __nv_bfloat16 g_Bp[(size_t)RNL * RNE * K3]; // codebook split [hi|hi|lo]

// ---------------- PTX helpers (sm_80-era only; no tcgen05 on plain sm_103) ----------------
__device__ __forceinline__ uint32_t smem_u32(const void* p) {
    uint32_t a;
    asm("{ .reg .u64 t; cvta.to.shared.u64 t, %1; cvt.u32.u64 %0, t; }" : "=r"(a) : "l"(p));
    return a;
}
__device__ __forceinline__ void cp16(uint32_t dst, const __nv_bfloat16* src) {
    asm volatile("cp.async.cg.shared.global [%0], [%1], 16;\n" :: "r"(dst),
                 "l"(__cvta_generic_to_global(src)));
}
__device__ __forceinline__ void cp_commit() {
    asm volatile("cp.async.commit_group;\n" ::: "memory");
}
template <int N>
__device__ __forceinline__ void cp_wait() {
    asm volatile("cp.async.wait_group %0;\n" :: "n"(N) : "memory");
}
__device__ __forceinline__ void ldsm4(uint32_t* r, uint32_t addr) {
    asm volatile("ldmatrix.sync.aligned.m8n8.x4.shared.b16 {%0,%1,%2,%3}, [%4];"
                 : "=r"(r[0]), "=r"(r[1]), "=r"(r[2]), "=r"(r[3]) : "r"(addr));
}
__device__ __forceinline__ void mma16816(float* c, const uint32_t* a, const uint32_t* b) {
    asm volatile(
        "mma.sync.aligned.m16n8k16.row.col.f32.bf16.bf16.f32 "
        "{%0,%1,%2,%3}, {%4,%5,%6,%7}, {%8,%9}, {%0,%1,%2,%3};"
        : "+f"(c[0]), "+f"(c[1]), "+f"(c[2]), "+f"(c[3])
        : "r"(a[0]), "r"(a[1]), "r"(a[2]), "r"(a[3]), "r"(b[0]), "r"(b[1]));
}

// split fp32 -> (hi, lo) bf16
__device__ __forceinline__ void split1(float x, __nv_bfloat16& h, __nv_bfloat16& l) {
    h = __float2bfloat16(x);
    l = __float2bfloat16(__fsub_rn(x, __bfloat162float(h)));
}

// ---------------- init: residual = x, rr, zero x_q, keys/loss, A' split ----------------
__global__ void k_init_rows(const float* __restrict__ x, float* __restrict__ out) {
    int b = blockIdx.x, t = threadIdx.x;  // 64 threads, one row per block
    float4 v = *(const float4*)(x + (size_t)b * RE + t * 4);
    *(float4*)(g_res + (size_t)b * RE + t * 4) = v;
    *(float4*)(out + (size_t)b * RE + t * 4) = make_float4(0.f, 0.f, 0.f, 0.f);

    __nv_bfloat16 h0, h1, h2, h3, l0, l1, l2, l3;
    split1(v.x, h0, l0); split1(v.y, h1, l1); split1(v.z, h2, l2); split1(v.w, h3, l3);
    __nv_bfloat16* ap = g_Ap + (size_t)b * K3 + t * 4;
    *(__nv_bfloat162*)(ap + 0) = __nv_bfloat162(h0, h1);
    *(__nv_bfloat162*)(ap + 2) = __nv_bfloat162(h2, h3);
    *(__nv_bfloat162*)(ap + 256) = __nv_bfloat162(l0, l1);
    *(__nv_bfloat162*)(ap + 258) = __nv_bfloat162(l2, l3);
    *(__nv_bfloat162*)(ap + 512) = __nv_bfloat162(h0, h1);
    *(__nv_bfloat162*)(ap + 514) = __nv_bfloat162(h2, h3);

    float s = v.x * v.x + v.y * v.y + v.z * v.z + v.w * v.w;
    for (int o = 16; o > 0; o >>= 1) s += __shfl_down_sync(0xffffffffu, s, o);
    __shared__ float sm[2];
    if ((t & 31) == 0) sm[t >> 5] = s;
    __syncthreads();
    if (t == 0) {
        g_rr[b] = sm[0] + sm[1];
        g_keys[b] = 0xFFFFFFFFFFFFFFFFULL;
        g_lossrow[b] = 0.f;
    }
}

// ---------------- codebook prep: B' split + exact cc ----------------
__global__ void k_prep_cb(const float* __restrict__ cbs) {
    int i = blockIdx.x, t = threadIdx.x;  // i in [0, 3*4096), 64 threads
    float4 v = *(const float4*)(cbs + (size_t)i * RE + t * 4);
    __nv_bfloat16 h0, h1, h2, h3, l0, l1, l2, l3;
    split1(v.x, h0, l0); split1(v.y, h1, l1); split1(v.z, h2, l2); split1(v.w, h3, l3);
    __nv_bfloat16* bp = g_Bp + (size_t)i * K3 + t * 4;
    *(__nv_bfloat162*)(bp + 0) = __nv_bfloat162(h0, h1);
    *(__nv_bfloat162*)(bp + 2) = __nv_bfloat162(h2, h3);
    *(__nv_bfloat162*)(bp + 256) = __nv_bfloat162(h0, h1);
    *(__nv_bfloat162*)(bp + 258) = __nv_bfloat162(h2, h3);
    *(__nv_bfloat162*)(bp + 512) = __nv_bfloat162(l0, l1);
    *(__nv_bfloat162*)(bp + 514) = __nv_bfloat162(l2, l3);

    float s = v.x * v.x + v.y * v.y + v.z * v.z + v.w * v.w;
    for (int o = 16; o > 0; o >>= 1) s += __shfl_down_sync(0xffffffffu, s, o);
    __shared__ float sm[2];
    if ((t & 31) == 0) sm[t >> 5] = s;
    __syncthreads();
    if (t == 0) g_cc[i] = sm[0] + sm[1];
}

// ---------------- zero the one-hot region ----------------
__global__ void k_zero_oh(float* __restrict__ out) {
    const size_t n4 = (LEN_OH - 3) / 4;
    float4* p = (float4*)(out + OFF_OH + 3);
    size_t i = (size_t)blockIdx.x * blockDim.x + threadIdx.x;
    size_t stride = (size_t)gridDim.x * blockDim.x;
    for (size_t j = i; j < n4; j += stride) p[j] = make_float4(0.f, 0.f, 0.f, 0.f);
    if (i == 0) {
        out[OFF_OH + 0] = 0.f;
        out[OFF_OH + 1] = 0.f;
        out[OFF_OH + 2] = 0.f;
        out[OFF_OH + 3 + n4 * 4] = 0.f;
    }
}

// ---------------- mma.sync distance GEMM + logits + argmin ----------------
// CTA 128x128, 8 warps (2 m x 4 n), warp tile 64x32, K=768 in 12 chunks of 64.
// smem: [0, 65536) two cp.async stages (A 16K + B 16K each); epilogue reuses
// [0, 67584) as fp32 [128][132].
#define DYN_SM 69632

__global__ void __launch_bounds__(256, 2) k_dist_tc(int l, float* __restrict__ out) {
    extern __shared__ __align__(16) char smraw[];
    uint32_t rawb = smem_u32(smraw);
    uint32_t sbase = (rawb + 1023u) & ~1023u;
    float* ep = (float*)(smraw + (sbase - rawb));  // epilogue staging [128][132]

    int tid = threadIdx.x, wid = tid >> 5, lane = tid & 31;
    int n0 = blockIdx.x * 128, m0 = blockIdx.y * 128;
    int warp_m = wid >> 2, warp_n = wid & 3;
    int mbw = warp_m * 64, nbw = warp_n * 32;
    int g = lane >> 2, tig = lane & 3;

    const __nv_bfloat16* Ap = g_Ap;
    const __nv_bfloat16* Bp = g_Bp + (size_t)l * RNE * K3;
    const float* ccn = g_cc + l * RNE;

    // per-lane ldmatrix address pieces
    uint32_t arow[4], axor[4];
#pragma unroll
    for (int i = 0; i < 4; i++) {
        int r = mbw + i * 16 + ((lane >> 3) & 1) * 8 + (lane & 7);
        arow[i] = (uint32_t)r * 128u;
        axor[i] = (uint32_t)((r & 7) << 4);
    }
    uint32_t koffA = (uint32_t)(((lane >> 4) & 1) * 16);
    uint32_t brow[2], bxor[2];
#pragma unroll
    for (int j2 = 0; j2 < 2; j2++) {
        int r = nbw + j2 * 16 + ((lane >> 4) & 1) * 8 + (lane & 7);
        brow[j2] = (uint32_t)r * 128u;
        bxor[j2] = (uint32_t)((r & 7) << 4);
    }
    uint32_t koffB = (uint32_t)(((lane >> 3) & 1) * 16);

    float acc[4][4][4];
#pragma unroll
    for (int i = 0; i < 4; i++)
#pragma unroll
        for (int j = 0; j < 4; j++)
#pragma unroll
            for (int r = 0; r < 4; r++) acc[i][j][r] = 0.f;

    // chunk loader: 128 rows x 64 bf16 (128B rows), SW128 swizzle, A then B
    auto load_chunk = [&](int c, int s) {
        uint32_t ab = sbase + s * 32768;
        uint32_t bb = ab + 16384;
        const __nv_bfloat16* ag = Ap + (size_t)m0 * K3 + c * 64;
        const __nv_bfloat16* bg = Bp + (size_t)n0 * K3 + c * 64;
#pragma unroll
        for (int i = 0; i < 4; i++) {
            int idx = tid + i * 256;
            int row = idx >> 3, q = idx & 7;
            uint32_t off = row * 128 + q * 16;
            uint32_t sw = off ^ ((off >> 3) & 0x70);
            cp16(ab + sw, ag + (size_t)row * K3 + q * 8);
        }
#pragma unroll
        for (int i = 0; i < 4; i++) {
            int idx = tid + i * 256;
            int row = idx >> 3, q = idx & 7;
            uint32_t off = row * 128 + q * 16;
            uint32_t sw = off ^ ((off >> 3) & 0x70);
            cp16(bb + sw, bg + (size_t)row * K3 + q * 8);
        }
        cp_commit();
    };

    load_chunk(0, 0);
    for (int c = 0; c < 12; c++) {
        int s = c & 1;
        if (c + 1 < 12) { load_chunk(c + 1, s ^ 1); cp_wait<1>(); }
        else cp_wait<0>();
        __syncthreads();

        uint32_t sA = sbase + s * 32768;
        uint32_t sB = sA + 16384;
#pragma unroll
        for (int ks = 0; ks < 4; ks++) {
            uint32_t a[4][4], b[2][4];
#pragma unroll
            for (int i = 0; i < 4; i++)
                ldsm4(a[i], sA + arow[i] + (((uint32_t)(ks * 32) + koffA) ^ axor[i]));
#pragma unroll
            for (int j2 = 0; j2 < 2; j2++)
                ldsm4(b[j2], sB + brow[j2] + (((uint32_t)(ks * 32) + koffB) ^ bxor[j2]));
#pragma unroll
            for (int i = 0; i < 4; i++)
#pragma unroll
                for (int j = 0; j < 4; j++)
                    mma16816(acc[i][j], a[i], &b[j >> 1][(j & 1) * 2]);
        }
        __syncthreads();
    }

    // ---- epilogue: d = (rr + cc) - 2*dot, argmin keys, stage logits ----
    float cc0[4], cc1[4];
#pragma unroll
    for (int j = 0; j < 4; j++) {
        cc0[j] = ccn[n0 + nbw + j * 8 + tig * 2];
        cc1[j] = ccn[n0 + nbw + j * 8 + tig * 2 + 1];
    }
#pragma unroll
    for (int i = 0; i < 4; i++) {
        int r0 = mbw + i * 16 + g, r1 = r0 + 8;
        float rr0 = g_rr[m0 + r0], rr1 = g_rr[m0 + r1];
        unsigned long long b0 = 0xFFFFFFFFFFFFFFFFULL, b1 = b0;
#pragma unroll
        for (int j = 0; j < 4; j++) {
            int coln = nbw + j * 8 + tig * 2;
            unsigned nlo = (unsigned)(n0 + coln), nhi = nlo + 1;
            float d00 = __fadd_rn(__fadd_rn(rr0, cc0[j]), -2.0f * acc[i][j][0]);
            float d01 = __fadd_rn(__fadd_rn(rr0, cc1[j]), -2.0f * acc[i][j][1]);
            float d10 = __fadd_rn(__fadd_rn(rr1, cc0[j]), -2.0f * acc[i][j][2]);
            float d11 = __fadd_rn(__fadd_rn(rr1, cc1[j]), -2.0f * acc[i][j][3]);
            *(float2*)(ep + r0 * 132 + coln) = make_float2(d00, d01);
            *(float2*)(ep + r1 * 132 + coln) = make_float2(d10, d11);
            unsigned long long k00 = ((unsigned long long)__float_as_uint(d00) << 32) | nlo;
            unsigned long long k01 = ((unsigned long long)__float_as_uint(d01) << 32) | nhi;
            unsigned long long k10 = ((unsigned long long)__float_as_uint(d10) << 32) | nlo;
            unsigned long long k11 = ((unsigned long long)__float_as_uint(d11) << 32) | nhi;
            if (k00 < b0) b0 = k00;
            if (k01 < b0) b0 = k01;
            if (k10 < b1) b1 = k10;
            if (k11 < b1) b1 = k11;
        }
        // reduce over the 4 lanes (tig) sharing each row
        b0 = min(b0, __shfl_xor_sync(0xffffffffu, b0, 1));
        b0 = min(b0, __shfl_xor_sync(0xffffffffu, b0, 2));
        b1 = min(b1, __shfl_xor_sync(0xffffffffu, b1, 1));
        b1 = min(b1, __shfl_xor_sync(0xffffffffu, b1, 2));
        if (tig == 0) {
            atomicMin(&g_keys[m0 + r0], b0);
            atomicMin(&g_keys[m0 + r1], b1);
        }
    }
    __syncthreads();

    // coalesced logits store: 256 threads, 2 rows per iteration
    int col = tid & 127, rsel = tid >> 7;
    for (int r = 0; r < 64; r++) {
        int row = r * 2 + rsel;
        out[OFF_LG + ((size_t)(m0 + row) * RNL + l) * RNE + n0 + col] = ep[row * 132 + col];
    }
}

// ---------------- per-row gather/update (+ refresh A' split) ----------------
__global__ void k_update(const float* __restrict__ cbs, int l, float* __restrict__ out) {
    int b = blockIdx.x, t = threadIdx.x;  // 64 threads
    unsigned long long key = g_keys[b];
    unsigned idx = (unsigned)(key & 0xFFFFFFFFULL);
    const float* cbL = cbs + (size_t)l * RNE * RE;
    float4 c4 = *(const float4*)(cbL + (size_t)idx * RE + t * 4);
    float4 r4 = *(float4*)(g_res + (size_t)b * RE + t * 4);

    float sq = 0.f, rrn = 0.f;
    float4 xres, nr;
#define STEP(comp)                                           \
    {                                                        \
        float df = __fsub_rn(c4.comp, r4.comp);              \
        float xr = __fadd_rn(r4.comp, df);                   \
        float nv = __fsub_rn(r4.comp, xr);                   \
        sq = fmaf(df, df, sq); rrn = fmaf(nv, nv, rrn);      \
        xres.comp = xr; nr.comp = nv;                        \
    }
    STEP(x) STEP(y) STEP(z) STEP(w)
#undef STEP

    *(float4*)(g_res + (size_t)b * RE + t * 4) = nr;

    if (l < RNL - 1) {  // refresh A' for next layer
        __nv_bfloat16 h0, h1, h2, h3, l0, l1, l2, l3;
        split1(nr.x, h0, l0); split1(nr.y, h1, l1); split1(nr.z, h2, l2); split1(nr.w, h3, l3);
        __nv_bfloat16* ap = g_Ap + (size_t)b * K3 + t * 4;
        *(__nv_bfloat162*)(ap + 0) = __nv_bfloat162(h0, h1);
        *(__nv_bfloat162*)(ap + 2) = __nv_bfloat162(h2, h3);
        *(__nv_bfloat162*)(ap + 256) = __nv_bfloat162(l0, l1);
        *(__nv_bfloat162*)(ap + 258) = __nv_bfloat162(l2, l3);
        *(__nv_bfloat162*)(ap + 512) = __nv_bfloat162(h0, h1);
        *(__nv_bfloat162*)(ap + 514) = __nv_bfloat162(h2, h3);
    }

    float4* xq = (float4*)(out + (size_t)b * RE) + t;
    float4 q = *xq;
    q.x += xres.x; q.y += xres.y; q.z += xres.z; q.w += xres.w;
    *xq = q;

    for (int o = 16; o > 0; o >>= 1) {
        sq += __shfl_down_sync(0xffffffffu, sq, o);
        rrn += __shfl_down_sync(0xffffffffu, rrn, o);
    }
    __shared__ float smq[2], smr[2];
    if ((t & 31) == 0) { smq[t >> 5] = sq; smr[t >> 5] = rrn; }
    __syncthreads();
    if (t == 0) {
        g_lossrow[b] += smq[0] + smq[1];
        g_rr[b] = smr[0] + smr[1];
        out[OFF_IDX + (size_t)b * RNL + l] = (float)idx;
        out[OFF_OH + ((size_t)b * RNL + l) * RNE + idx] = 1.0f;
        g_keys[b] = 0xFFFFFFFFFFFFFFFFULL;
    }
}

// ---------------- deterministic final loss ----------------
__global__ void k_loss(float* __restrict__ out) {
    __shared__ float sm[256];
    int t = threadIdx.x;
    float s = 0.f;
    for (int i = t; i < RB; i += 256) s += g_lossrow[i];
    sm[t] = s;
    __syncthreads();
    for (int o = 128; o > 0; o >>= 1) {
        if (t < o) sm[t] += sm[t + o];
        __syncthreads();
    }
    if (t == 0) out[OFF_LOSS] = sm[0] * (1.25f / (3.0f * RB * RE));
}

// ---------------- launch ----------------
extern "C" void kernel_launch(void* const* d_in, const int* in_sizes, int n_in,
                              void* d_out, int out_size) {
    const float* x = (const float*)d_in[0];
    const float* cbs = (const float*)d_in[1];
    float* out = (float*)d_out;

    cudaFuncSetAttribute(k_dist_tc, cudaFuncAttributeMaxDynamicSharedMemorySize, DYN_SM);

    k_init_rows<<<RB, 64>>>(x, out);
    k_prep_cb<<<RNL * RNE, 64>>>(cbs);
    k_zero_oh<<<12288, 256>>>(out);

    for (int l = 0; l < RNL; l++) {
        k_dist_tc<<<dim3(32, 64), 256, DYN_SM>>>(l, out);
        k_update<<<RB, 64>>>(cbs, l, out);
    }
    k_loss<<<1, 256>>>(out);
}

// round 4
// speedup vs baseline: 2.3258x; 1.0129x over previous
#include <cuda_runtime.h>
#include <cuda_bf16.h>
#include <cstdint>
#include <cstddef>

// ---------------- problem constants ----------------
#define RB 8192
#define RE 256
#define RNE 4096
#define RNL 3
#define K3 768           // split-bf16 K: [hi | lo | hi] x [hi | hi | lo]

// output layout (float32 elements), tuple order:
// x_q [B,E], mean_loss [1], all_idx [B,L], all_oh [B,L,NE], all_logits [B,L,NE]
static constexpr size_t LEN_XQ  = (size_t)RB * RE;                 // 2097152
static constexpr size_t OFF_LOSS = LEN_XQ;                         // 2097152
static constexpr size_t OFF_IDX  = OFF_LOSS + 1;                   // 2097153
static constexpr size_t LEN_IDX  = (size_t)RB * RNL;               // 24576
static constexpr size_t OFF_OH   = OFF_IDX + LEN_IDX;              // 2121729
static constexpr size_t LEN_OH   = (size_t)RB * RNL * RNE;         // 100663296
static constexpr size_t OFF_LG   = OFF_OH + LEN_OH;                // 102785025

// ---------------- device scratch ----------------
__device__ float g_res[RB * RE];                  // residual [B,E] fp32
__device__ float g_rr[RB];                        // ||residual_b||^2
__device__ float g_cc[RNL * RNE];                 // ||codebook row||^2 (fp32 exact)
__device__ unsigned long long g_keys[RB];         // packed (dist_bits<<32 | idx)
__device__ float g_lossrow[RB];                   // per-row accumulated sq error
__device__ __nv_bfloat16 g_Ap[(size_t)RB * K3];   // residual split  [hi|lo|hi]
__device__ __nv_bfloat16 g_Bp[(size_t)RNL * RNE * K3]; // codebook split [hi|hi|lo]

// ---------------- PTX helpers (sm_80-era only; no tcgen05 on plain sm_103) ----------------
__device__ __forceinline__ uint32_t smem_u32(const void* p) {
    uint32_t a;
    asm("{ .reg .u64 t; cvta.to.shared.u64 t, %1; cvt.u32.u64 %0, t; }" : "=r"(a) : "l"(p));
    return a;
}
__device__ __forceinline__ void cp16(uint32_t dst, const __nv_bfloat16* src) {
    asm volatile("cp.async.cg.shared.global [%0], [%1], 16;\n" :: "r"(dst),
                 "l"(__cvta_generic_to_global(src)));
}
__device__ __forceinline__ void cp_commit() {
    asm volatile("cp.async.commit_group;\n" ::: "memory");
}
template <int N>
__device__ __forceinline__ void cp_wait() {
    asm volatile("cp.async.wait_group %0;\n" :: "n"(N) : "memory");
}
__device__ __forceinline__ void ldsm4(uint32_t* r, uint32_t addr) {
    asm volatile("ldmatrix.sync.aligned.m8n8.x4.shared.b16 {%0,%1,%2,%3}, [%4];"
                 : "=r"(r[0]), "=r"(r[1]), "=r"(r[2]), "=r"(r[3]) : "r"(addr));
}
__device__ __forceinline__ void mma16816(float* c, const uint32_t* a, const uint32_t* b) {
    asm volatile(
        "mma.sync.aligned.m16n8k16.row.col.f32.bf16.bf16.f32 "
        "{%0,%1,%2,%3}, {%4,%5,%6,%7}, {%8,%9}, {%0,%1,%2,%3};"
        : "+f"(c[0]), "+f"(c[1]), "+f"(c[2]), "+f"(c[3])
        : "r"(a[0]), "r"(a[1]), "r"(a[2]), "r"(a[3]), "r"(b[0]), "r"(b[1]));
}

// split fp32 -> (hi, lo) bf16
__device__ __forceinline__ void split1(float x, __nv_bfloat16& h, __nv_bfloat16& l) {
    h = __float2bfloat16(x);
    l = __float2bfloat16(__fsub_rn(x, __bfloat162float(h)));
}

// ---------------- init: residual = x, rr, zero x_q, keys/loss, A' split ----------------
__global__ void k_init_rows(const float* __restrict__ x, float* __restrict__ out) {
    int b = blockIdx.x, t = threadIdx.x;  // 64 threads, one row per block
    float4 v = *(const float4*)(x + (size_t)b * RE + t * 4);
    *(float4*)(g_res + (size_t)b * RE + t * 4) = v;
    *(float4*)(out + (size_t)b * RE + t * 4) = make_float4(0.f, 0.f, 0.f, 0.f);

    __nv_bfloat16 h0, h1, h2, h3, l0, l1, l2, l3;
    split1(v.x, h0, l0); split1(v.y, h1, l1); split1(v.z, h2, l2); split1(v.w, h3, l3);
    __nv_bfloat16* ap = g_Ap + (size_t)b * K3 + t * 4;
    *(__nv_bfloat162*)(ap + 0) = __nv_bfloat162(h0, h1);
    *(__nv_bfloat162*)(ap + 2) = __nv_bfloat162(h2, h3);
    *(__nv_bfloat162*)(ap + 256) = __nv_bfloat162(l0, l1);
    *(__nv_bfloat162*)(ap + 258) = __nv_bfloat162(l2, l3);
    *(__nv_bfloat162*)(ap + 512) = __nv_bfloat162(h0, h1);
    *(__nv_bfloat162*)(ap + 514) = __nv_bfloat162(h2, h3);

    float s = v.x * v.x + v.y * v.y + v.z * v.z + v.w * v.w;
    for (int o = 16; o > 0; o >>= 1) s += __shfl_down_sync(0xffffffffu, s, o);
    __shared__ float sm[2];
    if ((t & 31) == 0) sm[t >> 5] = s;
    __syncthreads();
    if (t == 0) {
        g_rr[b] = sm[0] + sm[1];
        g_keys[b] = 0xFFFFFFFFFFFFFFFFULL;
        g_lossrow[b] = 0.f;
    }
}

// ---------------- codebook prep: B' split + exact cc ----------------
__global__ void k_prep_cb(const float* __restrict__ cbs) {
    int i = blockIdx.x, t = threadIdx.x;  // i in [0, 3*4096), 64 threads
    float4 v = *(const float4*)(cbs + (size_t)i * RE + t * 4);
    __nv_bfloat16 h0, h1, h2, h3, l0, l1, l2, l3;
    split1(v.x, h0, l0); split1(v.y, h1, l1); split1(v.z, h2, l2); split1(v.w, h3, l3);
    __nv_bfloat16* bp = g_Bp + (size_t)i * K3 + t * 4;
    *(__nv_bfloat162*)(bp + 0) = __nv_bfloat162(h0, h1);
    *(__nv_bfloat162*)(bp + 2) = __nv_bfloat162(h2, h3);
    *(__nv_bfloat162*)(bp + 256) = __nv_bfloat162(h0, h1);
    *(__nv_bfloat162*)(bp + 258) = __nv_bfloat162(h2, h3);
    *(__nv_bfloat162*)(bp + 512) = __nv_bfloat162(l0, l1);
    *(__nv_bfloat162*)(bp + 514) = __nv_bfloat162(l2, l3);

    float s = v.x * v.x + v.y * v.y + v.z * v.z + v.w * v.w;
    for (int o = 16; o > 0; o >>= 1) s += __shfl_down_sync(0xffffffffu, s, o);
    __shared__ float sm[2];
    if ((t & 31) == 0) sm[t >> 5] = s;
    __syncthreads();
    if (t == 0) g_cc[i] = sm[0] + sm[1];
}

// ---------------- zero the one-hot region ----------------
__global__ void k_zero_oh(float* __restrict__ out) {
    const size_t n4 = (LEN_OH - 3) / 4;
    float4* p = (float4*)(out + OFF_OH + 3);
    size_t i = (size_t)blockIdx.x * blockDim.x + threadIdx.x;
    size_t stride = (size_t)gridDim.x * blockDim.x;
    for (size_t j = i; j < n4; j += stride) p[j] = make_float4(0.f, 0.f, 0.f, 0.f);
    if (i == 0) {
        out[OFF_OH + 0] = 0.f;
        out[OFF_OH + 1] = 0.f;
        out[OFF_OH + 2] = 0.f;
        out[OFF_OH + 3 + n4 * 4] = 0.f;
    }
}

// ---------------- mma.sync distance GEMM + logits + argmin ----------------
// CTA 128x128, 4 warps (2m x 2n), warp tile 64x64, K=768 in 12 chunks of 64.
// 3-stage cp.async pipeline (32KB/stage), ONE __syncthreads per chunk.
// Epilogue reuses stage smem as fp32 [128][132].
#define DYN_SM 99328

__global__ void __launch_bounds__(128, 2) k_dist_tc(int l, float* __restrict__ out) {
    extern __shared__ __align__(16) char smraw[];
    uint32_t rawb = smem_u32(smraw);
    uint32_t sbase = (rawb + 1023u) & ~1023u;
    float* ep = (float*)(smraw + (sbase - rawb));  // epilogue staging [128][132]

    int tid = threadIdx.x, wid = tid >> 5, lane = tid & 31;
    int n0 = blockIdx.x * 128, m0 = blockIdx.y * 128;
    int warp_m = wid >> 1, warp_n = wid & 1;
    int mbw = warp_m * 64, nbw = warp_n * 64;
    int g = lane >> 2, tig = lane & 3;

    const __nv_bfloat16* Ap = g_Ap;
    const __nv_bfloat16* Bp = g_Bp + (size_t)l * RNE * K3;
    const float* ccn = g_cc + l * RNE;

    // per-lane ldmatrix address pieces (4 A frags of m16, 4 B frags of n16)
    uint32_t arow[4], axor[4], brow[4], bxor[4];
#pragma unroll
    for (int i = 0; i < 4; i++) {
        int r = mbw + i * 16 + ((lane >> 3) & 1) * 8 + (lane & 7);
        arow[i] = (uint32_t)r * 128u;
        axor[i] = (uint32_t)((r & 7) << 4);
    }
    uint32_t koffA = (uint32_t)(((lane >> 4) & 1) * 16);
#pragma unroll
    for (int j2 = 0; j2 < 4; j2++) {
        int r = nbw + j2 * 16 + ((lane >> 4) & 1) * 8 + (lane & 7);
        brow[j2] = (uint32_t)r * 128u;
        bxor[j2] = (uint32_t)((r & 7) << 4);
    }
    uint32_t koffB = (uint32_t)(((lane >> 3) & 1) * 16);

    float acc[4][8][4];
#pragma unroll
    for (int i = 0; i < 4; i++)
#pragma unroll
        for (int j = 0; j < 8; j++)
#pragma unroll
            for (int r = 0; r < 4; r++) acc[i][j][r] = 0.f;

    // chunk loader: 128 rows x 64 bf16 (128B rows), SW128 swizzle, A then B
    auto load_chunk = [&](int c, int s) {
        uint32_t ab = sbase + s * 32768;
        uint32_t bb = ab + 16384;
        const __nv_bfloat16* ag = Ap + (size_t)m0 * K3 + c * 64;
        const __nv_bfloat16* bg = Bp + (size_t)n0 * K3 + c * 64;
#pragma unroll
        for (int i = 0; i < 8; i++) {
            int idx = tid + i * 128;
            int row = idx >> 3, q = idx & 7;
            uint32_t off = row * 128 + q * 16;
            uint32_t sw = off ^ ((off >> 3) & 0x70);
            cp16(ab + sw, ag + (size_t)row * K3 + q * 8);
        }
#pragma unroll
        for (int i = 0; i < 8; i++) {
            int idx = tid + i * 128;
            int row = idx >> 3, q = idx & 7;
            uint32_t off = row * 128 + q * 16;
            uint32_t sw = off ^ ((off >> 3) & 0x70);
            cp16(bb + sw, bg + (size_t)row * K3 + q * 8);
        }
        cp_commit();
    };

    load_chunk(0, 0);
    load_chunk(1, 1);
    int stage_next = 2;
    for (int c = 0; c < 12; c++) {
        int s = c % 3;
        if (c == 11) cp_wait<0>(); else cp_wait<1>();
        __syncthreads();  // chunk c visible; also orders prior reads vs upcoming overwrite

        uint32_t sA = sbase + s * 32768;
        uint32_t sB = sA + 16384;
#pragma unroll
        for (int ks = 0; ks < 4; ks++) {
            uint32_t a[4][4], b[4][4];
#pragma unroll
            for (int i = 0; i < 4; i++)
                ldsm4(a[i], sA + arow[i] + (((uint32_t)(ks * 32) + koffA) ^ axor[i]));
#pragma unroll
            for (int j2 = 0; j2 < 4; j2++)
                ldsm4(b[j2], sB + brow[j2] + (((uint32_t)(ks * 32) + koffB) ^ bxor[j2]));
#pragma unroll
            for (int i = 0; i < 4; i++)
#pragma unroll
                for (int j = 0; j < 8; j++)
                    mma16816(acc[i][j], a[i], &b[j >> 1][(j & 1) * 2]);
        }
        if (c + 2 < 12) {
            load_chunk(c + 2, stage_next);
            stage_next = (stage_next + 1) % 3;
        }
    }
    __syncthreads();  // all warps done reading stages before epilogue reuses smem

    // ---- epilogue: d = (rr + cc) - 2*dot, argmin keys, stage logits ----
    float cc0[8], cc1[8];
#pragma unroll
    for (int j = 0; j < 8; j++) {
        cc0[j] = ccn[n0 + nbw + j * 8 + tig * 2];
        cc1[j] = ccn[n0 + nbw + j * 8 + tig * 2 + 1];
    }
#pragma unroll
    for (int i = 0; i < 4; i++) {
        int r0 = mbw + i * 16 + g, r1 = r0 + 8;
        float rr0 = g_rr[m0 + r0], rr1 = g_rr[m0 + r1];
        unsigned long long b0 = 0xFFFFFFFFFFFFFFFFULL, b1 = b0;
#pragma unroll
        for (int j = 0; j < 8; j++) {
            int coln = nbw + j * 8 + tig * 2;
            unsigned nlo = (unsigned)(n0 + coln), nhi = nlo + 1;
            float d00 = __fadd_rn(__fadd_rn(rr0, cc0[j]), -2.0f * acc[i][j][0]);
            float d01 = __fadd_rn(__fadd_rn(rr0, cc1[j]), -2.0f * acc[i][j][1]);
            float d10 = __fadd_rn(__fadd_rn(rr1, cc0[j]), -2.0f * acc[i][j][2]);
            float d11 = __fadd_rn(__fadd_rn(rr1, cc1[j]), -2.0f * acc[i][j][3]);
            *(float2*)(ep + r0 * 132 + coln) = make_float2(d00, d01);
            *(float2*)(ep + r1 * 132 + coln) = make_float2(d10, d11);
            unsigned long long k00 = ((unsigned long long)__float_as_uint(d00) << 32) | nlo;
            unsigned long long k01 = ((unsigned long long)__float_as_uint(d01) << 32) | nhi;
            unsigned long long k10 = ((unsigned long long)__float_as_uint(d10) << 32) | nlo;
            unsigned long long k11 = ((unsigned long long)__float_as_uint(d11) << 32) | nhi;
            if (k00 < b0) b0 = k00;
            if (k01 < b0) b0 = k01;
            if (k10 < b1) b1 = k10;
            if (k11 < b1) b1 = k11;
        }
        b0 = min(b0, __shfl_xor_sync(0xffffffffu, b0, 1));
        b0 = min(b0, __shfl_xor_sync(0xffffffffu, b0, 2));
        b1 = min(b1, __shfl_xor_sync(0xffffffffu, b1, 1));
        b1 = min(b1, __shfl_xor_sync(0xffffffffu, b1, 2));
        if (tig == 0) {
            atomicMin(&g_keys[m0 + r0], b0);
            atomicMin(&g_keys[m0 + r1], b1);
        }
    }
    __syncthreads();

    // coalesced logits store: 128 threads, one row per iteration
    for (int r = 0; r < 128; r++) {
        out[OFF_LG + ((size_t)(m0 + r) * RNL + l) * RNE + n0 + tid] = ep[r * 132 + tid];
    }
}

// ---------------- per-row gather/update (+ refresh A' split) ----------------
__global__ void k_update(const float* __restrict__ cbs, int l, float* __restrict__ out) {
    int b = blockIdx.x, t = threadIdx.x;  // 64 threads
    unsigned long long key = g_keys[b];
    unsigned idx = (unsigned)(key & 0xFFFFFFFFULL);
    const float* cbL = cbs + (size_t)l * RNE * RE;
    float4 c4 = *(const float4*)(cbL + (size_t)idx * RE + t * 4);
    float4 r4 = *(float4*)(g_res + (size_t)b * RE + t * 4);

    float sq = 0.f, rrn = 0.f;
    float4 xres, nr;
#define STEP(comp)                                           \
    {                                                        \
        float df = __fsub_rn(c4.comp, r4.comp);              \
        float xr = __fadd_rn(r4.comp, df);                   \
        float nv = __fsub_rn(r4.comp, xr);                   \
        sq = fmaf(df, df, sq); rrn = fmaf(nv, nv, rrn);      \
        xres.comp = xr; nr.comp = nv;                        \
    }
    STEP(x) STEP(y) STEP(z) STEP(w)
#undef STEP

    *(float4*)(g_res + (size_t)b * RE + t * 4) = nr;

    if (l < RNL - 1) {  // refresh A' for next layer
        __nv_bfloat16 h0, h1, h2, h3, l0, l1, l2, l3;
        split1(nr.x, h0, l0); split1(nr.y, h1, l1); split1(nr.z, h2, l2); split1(nr.w, h3, l3);
        __nv_bfloat16* ap = g_Ap + (size_t)b * K3 + t * 4;
        *(__nv_bfloat162*)(ap + 0) = __nv_bfloat162(h0, h1);
        *(__nv_bfloat162*)(ap + 2) = __nv_bfloat162(h2, h3);
        *(__nv_bfloat162*)(ap + 256) = __nv_bfloat162(l0, l1);
        *(__nv_bfloat162*)(ap + 258) = __nv_bfloat162(l2, l3);
        *(__nv_bfloat162*)(ap + 512) = __nv_bfloat162(h0, h1);
        *(__nv_bfloat162*)(ap + 514) = __nv_bfloat162(h2, h3);
    }

    float4* xq = (float4*)(out + (size_t)b * RE) + t;
    float4 q = *xq;
    q.x += xres.x; q.y += xres.y; q.z += xres.z; q.w += xres.w;
    *xq = q;

    for (int o = 16; o > 0; o >>= 1) {
        sq += __shfl_down_sync(0xffffffffu, sq, o);
        rrn += __shfl_down_sync(0xffffffffu, rrn, o);
    }
    __shared__ float smq[2], smr[2];
    if ((t & 31) == 0) { smq[t >> 5] = sq; smr[t >> 5] = rrn; }
    __syncthreads();
    if (t == 0) {
        g_lossrow[b] += smq[0] + smq[1];
        g_rr[b] = smr[0] + smr[1];
        out[OFF_IDX + (size_t)b * RNL + l] = (float)idx;
        out[OFF_OH + ((size_t)b * RNL + l) * RNE + idx] = 1.0f;
        g_keys[b] = 0xFFFFFFFFFFFFFFFFULL;
    }
}

// ---------------- deterministic final loss ----------------
__global__ void k_loss(float* __restrict__ out) {
    __shared__ float sm[256];
    int t = threadIdx.x;
    float s = 0.f;
    for (int i = t; i < RB; i += 256) s += g_lossrow[i];
    sm[t] = s;
    __syncthreads();
    for (int o = 128; o > 0; o >>= 1) {
        if (t < o) sm[t] += sm[t + o];
        __syncthreads();
    }
    if (t == 0) out[OFF_LOSS] = sm[0] * (1.25f / (3.0f * RB * RE));
}

// ---------------- launch ----------------
extern "C" void kernel_launch(void* const* d_in, const int* in_sizes, int n_in,
                              void* d_out, int out_size) {
    const float* x = (const float*)d_in[0];
    const float* cbs = (const float*)d_in[1];
    float* out = (float*)d_out;

    cudaFuncSetAttribute(k_dist_tc, cudaFuncAttributeMaxDynamicSharedMemorySize, DYN_SM);

    // Fork a side stream so the 402MB one-hot memset (DRAM-bound) overlaps the
    // layer-0 GEMM (tensor-bound). Streams/events are host objects (no device
    // allocations); capture-legal fork/join via events. Not destroyed (capture
    // holds references; only ~3 invocations total).
    cudaStream_t s1;
    cudaStreamCreateWithFlags(&s1, cudaStreamNonBlocking);
    cudaEvent_t e1, e2;
    cudaEventCreateWithFlags(&e1, cudaEventDisableTiming);
    cudaEventCreateWithFlags(&e2, cudaEventDisableTiming);

    cudaEventRecord(e1, 0);
    cudaStreamWaitEvent(s1, e1, 0);
    k_zero_oh<<<2048, 256, 0, s1>>>(out);
    cudaEventRecord(e2, s1);

    k_init_rows<<<RB, 64>>>(x, out);
    k_prep_cb<<<RNL * RNE, 64>>>(cbs);

    for (int l = 0; l < RNL; l++) {
        k_dist_tc<<<dim3(32, 64), 128, DYN_SM>>>(l, out);
        if (l == 0) cudaStreamWaitEvent(0, e2, 0);  // one-hot zero must precede first update
        k_update<<<RB, 64>>>(cbs, l, out);
    }
    k_loss<<<1, 256>>>(out);
}